// round 3
// baseline (speedup 1.0000x reference)
#include <cuda_runtime.h>

#define NN 100000
#define EE 1600000
#define CC 128
#define SCAN_BS 1024
#define NB_MAX 128

// ---- static device scratch ----
__device__ int   g_deg[NN];
__device__ int   g_start[NN];
__device__ int   g_fill[NN];
__device__ int   g_col[EE];
__device__ float g_Y[(size_t)NN * CC];
__device__ int   g_bsums[NB_MAX];
__device__ int   g_is64;

// ---------------- detect dtype + zero degree array (fused) ----------------
__global__ void k_detect_zero(const int* __restrict__ ei32, int n) {
    int i = blockIdx.x * blockDim.x + threadIdx.x;
    if (i < n) g_deg[i] = 0;
    if (i == 0) {
        int nonzero_hi = 0;
        #pragma unroll 1
        for (int t = 0; t < 64; t++) {
            if (ei32[2 * t + 1] != 0) nonzero_hi++;
        }
        g_is64 = (nonzero_hi == 0) ? 1 : 0;
    }
}

__device__ __forceinline__ int load_edge(const void* ei, int idx, int is64) {
    if (is64) return (int)((const long long*)ei)[idx];
    return ((const int*)ei)[idx];
}

// ---------------- CSR build ----------------
__global__ void k_hist(const void* __restrict__ ei, int e) {
    int i = blockIdx.x * blockDim.x + threadIdx.x;
    if (i < e) {
        int dst = load_edge(ei, e + i, g_is64);
        if ((unsigned)dst < (unsigned)NN)
            atomicAdd(&g_deg[dst], 1);
    }
}

__global__ void k_scan1(int n) {
    __shared__ int sh[SCAN_BS];
    int tid = threadIdx.x;
    int i = blockIdx.x * SCAN_BS + tid;
    int v = (i < n) ? g_deg[i] : 0;
    sh[tid] = v;
    __syncthreads();
    #pragma unroll
    for (int off = 1; off < SCAN_BS; off <<= 1) {
        int t = 0;
        if (tid >= off) t = sh[tid - off];
        __syncthreads();
        if (tid >= off) sh[tid] += t;
        __syncthreads();
    }
    int incl = sh[tid];
    if (i < n) g_start[i] = incl - v;
    if (tid == SCAN_BS - 1) g_bsums[blockIdx.x] = incl;
}

__global__ void k_scan2(int nb) {
    if (threadIdx.x == 0) {
        int run = 0;
        for (int b = 0; b < nb; b++) { int t = g_bsums[b]; g_bsums[b] = run; run += t; }
    }
}

__global__ void k_scan3(int n) {
    int i = blockIdx.x * blockDim.x + threadIdx.x;
    if (i < n) {
        int s = g_start[i] + g_bsums[i >> 10];
        g_start[i] = s;
        g_fill[i]  = s;
    }
}

__global__ void k_fill(const void* __restrict__ ei, int e) {
    int i = blockIdx.x * blockDim.x + threadIdx.x;
    if (i < e) {
        int is64 = g_is64;
        int dst = load_edge(ei, e + i, is64);
        int src = load_edge(ei, i, is64);
        if ((unsigned)dst < (unsigned)NN && (unsigned)src < (unsigned)NN) {
            int pos = atomicAdd(&g_fill[dst], 1);
            if ((unsigned)pos < (unsigned)EE)
                g_col[pos] = src;
        }
    }
}

// ---------------- helpers for packed f32x2 ----------------
__device__ __forceinline__ unsigned long long dup_f32(float x) {
    unsigned u = __float_as_uint(x);
    unsigned long long d;
    asm("mov.b64 %0, {%1, %1};" : "=l"(d) : "r"(u));
    return d;
}
__device__ __forceinline__ float2 unpk(unsigned long long v) {
    unsigned lo, hi;
    asm("mov.b64 {%0, %1}, %2;" : "=r"(lo), "=r"(hi) : "l"(v));
    return make_float2(__uint_as_float(lo), __uint_as_float(hi));
}

// ---------------- GEMM: Y = data @ W  via packed fma.rn.f32x2 ----------------
// Block tile 256(M) x 128(N), K-tile 16, 256 threads, 16x8 microtile/thread.
// acc2[i][j] = {C[m0+ty*16+2i][n], C[m0+ty*16+2i+1][n]},  n = tx*8+j.
__global__ void __launch_bounds__(256, 1) k_gemm(const float* __restrict__ A,
                                                 const float* __restrict__ W, int M) {
    __shared__ __align__(16) float As[16][260];                 // transposed, padded
    __shared__ __align__(16) unsigned long long Wd[16][8][16];  // dup'd: [kk][j][tx]

    int tid = threadIdx.x;
    int tx = tid & 15;
    int ty = tid >> 4;
    int m0 = blockIdx.x * 256;

    unsigned long long acc2[8][8];
    #pragma unroll
    for (int i = 0; i < 8; i++)
        #pragma unroll
        for (int j = 0; j < 8; j++) acc2[i][j] = 0ull;

    float4 rA[4];
    float4 rW0, rW1;
    const int wkk = ty;        // 0..15 : kk row this thread stages for W
    const int wn0 = tx * 8;    // n base

    // preload k0 = 0
    #pragma unroll
    for (int r = 0; r < 4; r++) {
        int idx = tid + 256 * r;
        int m = idx >> 2, kq = (idx & 3) * 4;
        int row = m0 + m;
        rA[r] = (row < M) ? *(const float4*)(A + (size_t)row * 128 + kq)
                          : make_float4(0.f, 0.f, 0.f, 0.f);
    }
    rW0 = *(const float4*)(W + (size_t)wkk * 128 + wn0);
    rW1 = *(const float4*)(W + (size_t)wkk * 128 + wn0 + 4);

    #pragma unroll 1
    for (int t = 0; t < 8; t++) {
        // commit staged tile to SMEM
        #pragma unroll
        for (int r = 0; r < 4; r++) {
            int idx = tid + 256 * r;
            int m = idx >> 2, kq = (idx & 3) * 4;
            As[kq + 0][m] = rA[r].x; As[kq + 1][m] = rA[r].y;
            As[kq + 2][m] = rA[r].z; As[kq + 3][m] = rA[r].w;
        }
        Wd[wkk][0][tx] = dup_f32(rW0.x);
        Wd[wkk][1][tx] = dup_f32(rW0.y);
        Wd[wkk][2][tx] = dup_f32(rW0.z);
        Wd[wkk][3][tx] = dup_f32(rW0.w);
        Wd[wkk][4][tx] = dup_f32(rW1.x);
        Wd[wkk][5][tx] = dup_f32(rW1.y);
        Wd[wkk][6][tx] = dup_f32(rW1.z);
        Wd[wkk][7][tx] = dup_f32(rW1.w);
        __syncthreads();

        // prefetch next K-tile while computing this one
        if (t < 7) {
            int k0n = (t + 1) * 16;
            #pragma unroll
            for (int r = 0; r < 4; r++) {
                int idx = tid + 256 * r;
                int m = idx >> 2, kq = (idx & 3) * 4;
                int row = m0 + m;
                rA[r] = (row < M) ? *(const float4*)(A + (size_t)row * 128 + k0n + kq)
                                  : make_float4(0.f, 0.f, 0.f, 0.f);
            }
            rW0 = *(const float4*)(W + (size_t)(k0n + wkk) * 128 + wn0);
            rW1 = *(const float4*)(W + (size_t)(k0n + wkk) * 128 + wn0 + 4);
        }

        #pragma unroll
        for (int kk = 0; kk < 16; kk++) {
            unsigned long long a2[8], b2[8];
            const ulonglong2* ap = (const ulonglong2*)&As[kk][ty * 16];
            #pragma unroll
            for (int q = 0; q < 4; q++) {
                ulonglong2 v = ap[q];
                a2[2 * q]     = v.x;
                a2[2 * q + 1] = v.y;
            }
            #pragma unroll
            for (int j = 0; j < 8; j++) b2[j] = Wd[kk][j][tx];
            #pragma unroll
            for (int i = 0; i < 8; i++)
                #pragma unroll
                for (int j = 0; j < 8; j++)
                    asm("fma.rn.f32x2 %0, %1, %2, %0;"
                        : "+l"(acc2[i][j]) : "l"(a2[i]), "l"(b2[j]));
        }
        __syncthreads();
    }

    // epilogue: each acc2[i][*] holds two consecutive m rows
    #pragma unroll
    for (int i = 0; i < 8; i++) {
        float2 c[8];
        #pragma unroll
        for (int j = 0; j < 8; j++) c[j] = unpk(acc2[i][j]);
        int mlo = m0 + ty * 16 + 2 * i;
        if (mlo < M) {
            *(float4*)(g_Y + (size_t)mlo * 128 + tx * 8) =
                make_float4(c[0].x, c[1].x, c[2].x, c[3].x);
            *(float4*)(g_Y + (size_t)mlo * 128 + tx * 8 + 4) =
                make_float4(c[4].x, c[5].x, c[6].x, c[7].x);
        }
        if (mlo + 1 < M) {
            *(float4*)(g_Y + (size_t)(mlo + 1) * 128 + tx * 8) =
                make_float4(c[0].y, c[1].y, c[2].y, c[3].y);
            *(float4*)(g_Y + (size_t)(mlo + 1) * 128 + tx * 8 + 4) =
                make_float4(c[4].y, c[5].y, c[6].y, c[7].y);
        }
    }
}

// ---------------- Aggregate + bias + GroupNorm(4) + ReLU ----------------
__global__ void __launch_bounds__(256) k_agg(const float* __restrict__ bias,
                                             const float* __restrict__ gamma,
                                             const float* __restrict__ beta,
                                             float* __restrict__ out, int n) {
    int w = (blockIdx.x * blockDim.x + threadIdx.x) >> 5;
    int lane = threadIdx.x & 31;
    if (w >= n) return;

    int start = g_start[w];
    int deg   = g_deg[w];

    float ax = 0.f, ay = 0.f, az = 0.f, aw = 0.f;
    int i = 0;
    for (; i + 4 <= deg; i += 4) {
        int c0 = g_col[start + i];
        int c1 = g_col[start + i + 1];
        int c2 = g_col[start + i + 2];
        int c3 = g_col[start + i + 3];
        float4 v0 = *(const float4*)(g_Y + (size_t)c0 * 128 + lane * 4);
        float4 v1 = *(const float4*)(g_Y + (size_t)c1 * 128 + lane * 4);
        float4 v2 = *(const float4*)(g_Y + (size_t)c2 * 128 + lane * 4);
        float4 v3 = *(const float4*)(g_Y + (size_t)c3 * 128 + lane * 4);
        ax += v0.x + v1.x + v2.x + v3.x;
        ay += v0.y + v1.y + v2.y + v3.y;
        az += v0.z + v1.z + v2.z + v3.z;
        aw += v0.w + v1.w + v2.w + v3.w;
    }
    for (; i < deg; i++) {
        int c = g_col[start + i];
        float4 v = *(const float4*)(g_Y + (size_t)c * 128 + lane * 4);
        ax += v.x; ay += v.y; az += v.z; aw += v.w;
    }

    float inv = 1.0f / (float)(deg > 1 ? deg : 1);
    float4 bb = ((const float4*)bias)[lane];
    float x0 = ax * inv + bb.x;
    float x1 = ay * inv + bb.y;
    float x2 = az * inv + bb.z;
    float x3 = aw * inv + bb.w;

    float s  = x0 + x1 + x2 + x3;
    float ss = x0 * x0 + x1 * x1 + x2 * x2 + x3 * x3;
    #pragma unroll
    for (int o = 1; o < 8; o <<= 1) {
        s  += __shfl_xor_sync(0xffffffffu, s, o);
        ss += __shfl_xor_sync(0xffffffffu, ss, o);
    }
    float mu   = s * (1.0f / 32.0f);
    float var  = ss * (1.0f / 32.0f) - mu * mu;
    float rstd = rsqrtf(var + 1e-5f);

    float4 gg = ((const float4*)gamma)[lane];
    float4 be = ((const float4*)beta)[lane];
    float y0 = fmaxf((x0 - mu) * rstd * gg.x + be.x, 0.f);
    float y1 = fmaxf((x1 - mu) * rstd * gg.y + be.y, 0.f);
    float y2 = fmaxf((x2 - mu) * rstd * gg.z + be.z, 0.f);
    float y3 = fmaxf((x3 - mu) * rstd * gg.w + be.w, 0.f);

    *(float4*)(out + (size_t)w * 128 + lane * 4) = make_float4(y0, y1, y2, y3);
}

// ---------------- launch ----------------
extern "C" void kernel_launch(void* const* d_in, const int* in_sizes, int n_in,
                              void* d_out, int out_size) {
    const float* data  = (const float*)d_in[0];
    const float* W     = (const float*)d_in[1];
    const float* b     = (const float*)d_in[2];
    const float* gamma = (const float*)d_in[3];
    const float* beta  = (const float*)d_in[4];
    const void*  ei    = d_in[5];

    int n = in_sizes[0] / CC;
    int e = in_sizes[5] / 2;

    k_detect_zero<<<(n + 255) / 256, 256>>>((const int*)ei, n);      // 0
    k_hist<<<(e + 255) / 256, 256>>>(ei, e);                         // 1
    int nb = (n + SCAN_BS - 1) / SCAN_BS;
    k_scan1<<<nb, SCAN_BS>>>(n);                                     // 2
    k_gemm<<<(n + 255) / 256, 256>>>(data, W, n);                    // 3 (independent)
    k_scan2<<<1, 32>>>(nb);                                          // 4
    k_scan3<<<(n + 255) / 256, 256>>>(n);                            // 5
    k_fill<<<(e + 255) / 256, 256>>>(ei, e);                         // 6
    k_agg<<<(n + 7) / 8, 256>>>(b, gamma, beta, (float*)d_out, n);   // 7
}

// round 5
// speedup vs baseline: 1.5124x; 1.5124x over previous
#include <cuda_runtime.h>
#include <cuda_bf16.h>
#include <cstdint>

#define NN 100000
#define EE 1600000
#define CC 128
#define SCAN_BS 1024
#define NB_MAX 128

// ---- static device scratch ----
__device__ int   g_deg[NN];
__device__ int   g_start[NN];
__device__ int   g_fill[NN];
__device__ int   g_col[EE];
__device__ float g_Y[(size_t)NN * CC];
__device__ int   g_bsums[NB_MAX];
__device__ int   g_is64;
// W transposed + bf16-split: Wt[n][k], n-major, 128x128 bf16 each
__device__ __align__(16) unsigned short g_wthi[16384];
__device__ __align__(16) unsigned short g_wtlo[16384];

// =================== detect + CSR build ===================
__global__ void k_detect_zero(const int* __restrict__ ei32, int n) {
    int i = blockIdx.x * blockDim.x + threadIdx.x;
    if (i < n) g_deg[i] = 0;
    if (i == 0) {
        int nz = 0;
        #pragma unroll 1
        for (int t = 0; t < 64; t++) if (ei32[2 * t + 1] != 0) nz++;
        g_is64 = (nz == 0) ? 1 : 0;
    }
}

__device__ __forceinline__ int load_edge(const void* ei, int idx, int is64) {
    if (is64) return (int)((const long long*)ei)[idx];
    return ((const int*)ei)[idx];
}

__global__ void k_hist(const void* __restrict__ ei, int e) {
    int i = blockIdx.x * blockDim.x + threadIdx.x;
    if (i < e) {
        int dst = load_edge(ei, e + i, g_is64);
        if ((unsigned)dst < (unsigned)NN) atomicAdd(&g_deg[dst], 1);
    }
}

__global__ void k_scan1(int n) {
    __shared__ int sh[SCAN_BS];
    int tid = threadIdx.x;
    int i = blockIdx.x * SCAN_BS + tid;
    int v = (i < n) ? g_deg[i] : 0;
    sh[tid] = v;
    __syncthreads();
    #pragma unroll
    for (int off = 1; off < SCAN_BS; off <<= 1) {
        int t = 0;
        if (tid >= off) t = sh[tid - off];
        __syncthreads();
        if (tid >= off) sh[tid] += t;
        __syncthreads();
    }
    int incl = sh[tid];
    if (i < n) g_start[i] = incl - v;
    if (tid == SCAN_BS - 1) g_bsums[blockIdx.x] = incl;
}

__global__ void k_scan2(int nb) {
    if (threadIdx.x == 0) {
        int run = 0;
        for (int b = 0; b < nb; b++) { int t = g_bsums[b]; g_bsums[b] = run; run += t; }
    }
}

__global__ void k_scan3(int n) {
    int i = blockIdx.x * blockDim.x + threadIdx.x;
    if (i < n) {
        int s = g_start[i] + g_bsums[i >> 10];
        g_start[i] = s;
        g_fill[i]  = s;
    }
}

__global__ void k_fill(const void* __restrict__ ei, int e) {
    int i = blockIdx.x * blockDim.x + threadIdx.x;
    if (i < e) {
        int is64 = g_is64;
        int dst = load_edge(ei, e + i, is64);
        int src = load_edge(ei, i, is64);
        if ((unsigned)dst < (unsigned)NN && (unsigned)src < (unsigned)NN) {
            int pos = atomicAdd(&g_fill[dst], 1);
            if ((unsigned)pos < (unsigned)EE) g_col[pos] = src;
        }
    }
}

// =================== W prep: transpose + bf16 split ===================
__device__ __forceinline__ unsigned short bfb(__nv_bfloat16 v) {
    return *reinterpret_cast<unsigned short*>(&v);
}
__global__ void k_wprep(const float* __restrict__ W) {
    int i = blockIdx.x * blockDim.x + threadIdx.x;
    if (i < 16384) {
        int k = i >> 7, n = i & 127;
        float x = W[i];                       // W[k][n]
        __nv_bfloat16 h = __float2bfloat16(x);
        __nv_bfloat16 l = __float2bfloat16(x - __bfloat162float(h));
        g_wthi[n * 128 + k] = bfb(h);         // Wt[n][k]
        g_wtlo[n * 128 + k] = bfb(l);
    }
}

// =================== GEMM: Y = data @ W via mma.sync bf16x3 ===================
// CTA: 256 thr = 8 warps, BM=256 (32 rows/warp), N=128, K=128.
// smem: Wt hi/lo, row stride 272B (16B pad -> conflict-free B loads).
#define WROW 272
#define SM_WHI 0
#define SM_WLO (128 * WROW)
#define SM_TOT (2 * 128 * WROW)   // 69632

__device__ __forceinline__ unsigned pk2f(float a, float b) {
    __nv_bfloat16 ha = __float2bfloat16(a), hb = __float2bfloat16(b);
    return (unsigned)bfb(ha) | ((unsigned)bfb(hb) << 16);
}
__device__ __forceinline__ void split2(float2 f, unsigned& hi, unsigned& lo) {
    __nv_bfloat16 hx = __float2bfloat16(f.x);
    __nv_bfloat16 hy = __float2bfloat16(f.y);
    hi = (unsigned)bfb(hx) | ((unsigned)bfb(hy) << 16);
    lo = pk2f(f.x - __bfloat162float(hx), f.y - __bfloat162float(hy));
}
__device__ __forceinline__ void mma16816(float* c, unsigned a0, unsigned a1,
                                         unsigned a2, unsigned a3,
                                         unsigned b0, unsigned b1) {
    asm volatile(
        "mma.sync.aligned.m16n8k16.row.col.f32.bf16.bf16.f32 "
        "{%0,%1,%2,%3}, {%4,%5,%6,%7}, {%8,%9}, {%0,%1,%2,%3};"
        : "+f"(c[0]), "+f"(c[1]), "+f"(c[2]), "+f"(c[3])
        : "r"(a0), "r"(a1), "r"(a2), "r"(a3), "r"(b0), "r"(b1));
}

__global__ void __launch_bounds__(256, 1) k_gemm_mma(const float* __restrict__ A, int M) {
    extern __shared__ unsigned char smem[];
    int tid = threadIdx.x;
    int w = tid >> 5, lane = tid & 31;
    int g = lane >> 2, tic = lane & 3;
    int mb = blockIdx.x * 256 + w * 32;

    // copy Wt images into padded smem
    {
        const uint4* sh = (const uint4*)g_wthi;
        const uint4* sl = (const uint4*)g_wtlo;
        uint4* dh = (uint4*)(smem + SM_WHI);
        uint4* dl = (uint4*)(smem + SM_WLO);
        #pragma unroll
        for (int r = 0; r < 8; r++) {
            int i = tid + 256 * r;            // 0..2047
            int row = i >> 4, col = i & 15;
            dh[row * 17 + col] = sh[i];
            dl[row * 17 + col] = sl[i];
        }
    }
    __syncthreads();

    float acc[2][16][4];
    #pragma unroll
    for (int mt = 0; mt < 2; mt++)
        #pragma unroll
        for (int nt = 0; nt < 16; nt++)
            #pragma unroll
            for (int q = 0; q < 4; q++) acc[mt][nt][q] = 0.f;

    // row indices for A fragments (2 m-tiles of 16)
    int rows[4] = { mb + g, mb + g + 8, mb + g + 16, mb + g + 24 };
    bool rok[4] = { rows[0] < M, rows[1] < M, rows[2] < M, rows[3] < M };

    // fa[mt*4 + kp*2 + rr] : rr = row g / g+8 within mtile, kp = k-offset 0/8
    float2 fa[8];
    auto lda = [&](int ks) {
        #pragma unroll
        for (int mt = 0; mt < 2; mt++)
            #pragma unroll
            for (int kp = 0; kp < 2; kp++)
                #pragma unroll
                for (int rr = 0; rr < 2; rr++) {
                    int r = rows[mt * 2 + rr];
                    int c = ks * 16 + kp * 8 + tic * 2;
                    fa[mt * 4 + kp * 2 + rr] =
                        rok[mt * 2 + rr] ? *(const float2*)(A + (size_t)r * 128 + c)
                                         : make_float2(0.f, 0.f);
                }
    };

    lda(0);
    unsigned ah[8], al[8];

    #pragma unroll 1
    for (int ks = 0; ks < 8; ks++) {
        #pragma unroll
        for (int q = 0; q < 8; q++) split2(fa[q], ah[q], al[q]);
        if (ks < 7) lda(ks + 1);

        unsigned kbyte = (unsigned)(ks * 32 + tic * 4);
        #pragma unroll
        for (int nt = 0; nt < 16; nt++) {
            const unsigned char* bh = smem + SM_WHI + (nt * 8 + g) * WROW + kbyte;
            const unsigned char* bl = smem + SM_WLO + (nt * 8 + g) * WROW + kbyte;
            unsigned bh0 = *(const unsigned*)bh;
            unsigned bh1 = *(const unsigned*)(bh + 16);
            unsigned bl0 = *(const unsigned*)bl;
            unsigned bl1 = *(const unsigned*)(bl + 16);
            #pragma unroll
            for (int mt = 0; mt < 2; mt++) {
                unsigned a0 = ah[mt * 4 + 0], a1 = ah[mt * 4 + 1];
                unsigned a2 = ah[mt * 4 + 2], a3 = ah[mt * 4 + 3];
                mma16816(acc[mt][nt], a0, a1, a2, a3, bh0, bh1);
                mma16816(acc[mt][nt], a0, a1, a2, a3, bl0, bl1);
                mma16816(acc[mt][nt],
                         al[mt * 4 + 0], al[mt * 4 + 1],
                         al[mt * 4 + 2], al[mt * 4 + 3], bh0, bh1);
            }
        }
    }

    // epilogue: c0,c1 -> row g, cols 2tic..; c2,c3 -> row g+8
    #pragma unroll
    for (int mt = 0; mt < 2; mt++) {
        int r0 = mb + mt * 16 + g;
        int r1 = r0 + 8;
        #pragma unroll
        for (int nt = 0; nt < 16; nt++) {
            int c = nt * 8 + tic * 2;
            if (r0 < M)
                *(float2*)(g_Y + (size_t)r0 * 128 + c) =
                    make_float2(acc[mt][nt][0], acc[mt][nt][1]);
            if (r1 < M)
                *(float2*)(g_Y + (size_t)r1 * 128 + c) =
                    make_float2(acc[mt][nt][2], acc[mt][nt][3]);
        }
    }
}

// =================== Aggregate + bias + GroupNorm(4) + ReLU ===================
__global__ void __launch_bounds__(256) k_agg(const float* __restrict__ bias,
                                             const float* __restrict__ gamma,
                                             const float* __restrict__ beta,
                                             float* __restrict__ out, int n) {
    int w = (blockIdx.x * blockDim.x + threadIdx.x) >> 5;
    int lane = threadIdx.x & 31;
    if (w >= n) return;

    int start = g_start[w];
    int deg   = g_deg[w];

    float ax = 0.f, ay = 0.f, az = 0.f, aw = 0.f;
    int i = 0;
    for (; i + 4 <= deg; i += 4) {
        int c0 = g_col[start + i];
        int c1 = g_col[start + i + 1];
        int c2 = g_col[start + i + 2];
        int c3 = g_col[start + i + 3];
        float4 v0 = *(const float4*)(g_Y + (size_t)c0 * 128 + lane * 4);
        float4 v1 = *(const float4*)(g_Y + (size_t)c1 * 128 + lane * 4);
        float4 v2 = *(const float4*)(g_Y + (size_t)c2 * 128 + lane * 4);
        float4 v3 = *(const float4*)(g_Y + (size_t)c3 * 128 + lane * 4);
        ax += v0.x + v1.x + v2.x + v3.x;
        ay += v0.y + v1.y + v2.y + v3.y;
        az += v0.z + v1.z + v2.z + v3.z;
        aw += v0.w + v1.w + v2.w + v3.w;
    }
    for (; i < deg; i++) {
        int c = g_col[start + i];
        float4 v = *(const float4*)(g_Y + (size_t)c * 128 + lane * 4);
        ax += v.x; ay += v.y; az += v.z; aw += v.w;
    }

    float inv = 1.0f / (float)(deg > 1 ? deg : 1);
    float4 bb = ((const float4*)bias)[lane];
    float x0 = ax * inv + bb.x;
    float x1 = ay * inv + bb.y;
    float x2 = az * inv + bb.z;
    float x3 = aw * inv + bb.w;

    float s  = x0 + x1 + x2 + x3;
    float ss = x0 * x0 + x1 * x1 + x2 * x2 + x3 * x3;
    #pragma unroll
    for (int o = 1; o < 8; o <<= 1) {
        s  += __shfl_xor_sync(0xffffffffu, s, o);
        ss += __shfl_xor_sync(0xffffffffu, ss, o);
    }
    float mu   = s * (1.0f / 32.0f);
    float var  = ss * (1.0f / 32.0f) - mu * mu;
    float rstd = rsqrtf(var + 1e-5f);

    float4 gg = ((const float4*)gamma)[lane];
    float4 be = ((const float4*)beta)[lane];
    float y0 = fmaxf((x0 - mu) * rstd * gg.x + be.x, 0.f);
    float y1 = fmaxf((x1 - mu) * rstd * gg.y + be.y, 0.f);
    float y2 = fmaxf((x2 - mu) * rstd * gg.z + be.z, 0.f);
    float y3 = fmaxf((x3 - mu) * rstd * gg.w + be.w, 0.f);

    *(float4*)(out + (size_t)w * 128 + lane * 4) = make_float4(y0, y1, y2, y3);
}

// =================== launch ===================
extern "C" void kernel_launch(void* const* d_in, const int* in_sizes, int n_in,
                              void* d_out, int out_size) {
    const float* data  = (const float*)d_in[0];
    const float* W     = (const float*)d_in[1];
    const float* b     = (const float*)d_in[2];
    const float* gamma = (const float*)d_in[3];
    const float* beta  = (const float*)d_in[4];
    const void*  ei    = d_in[5];

    int n = in_sizes[0] / CC;
    int e = in_sizes[5] / 2;

    static cudaStream_t s1 = nullptr;
    static cudaEvent_t evA = nullptr, evB = nullptr;
    if (!s1) {
        cudaStreamCreateWithFlags(&s1, cudaStreamNonBlocking);
        cudaEventCreateWithFlags(&evA, cudaEventDisableTiming);
        cudaEventCreateWithFlags(&evB, cudaEventDisableTiming);
        cudaFuncSetAttribute(k_gemm_mma, cudaFuncAttributeMaxDynamicSharedMemorySize, SM_TOT);
    }

    // fork: CSR chain on s1, GEMM path on main stream
    cudaEventRecord(evA, 0);
    cudaStreamWaitEvent(s1, evA, 0);

    k_detect_zero<<<(n + 255) / 256, 256, 0, s1>>>((const int*)ei, n);
    k_hist<<<(e + 255) / 256, 256, 0, s1>>>(ei, e);
    int nb = (n + SCAN_BS - 1) / SCAN_BS;
    k_scan1<<<nb, SCAN_BS, 0, s1>>>(n);
    k_scan2<<<1, 32, 0, s1>>>(nb);
    k_scan3<<<(n + 255) / 256, 256, 0, s1>>>(n);
    k_fill<<<(e + 255) / 256, 256, 0, s1>>>(ei, e);

    k_wprep<<<128, 128>>>(W);
    k_gemm_mma<<<(n + 255) / 256, 256, SM_TOT>>>(data, n);

    // join
    cudaEventRecord(evB, s1);
    cudaStreamWaitEvent((cudaStream_t)0, evB, 0);

    k_agg<<<(n + 7) / 8, 256>>>(b, gamma, beta, (float*)d_out, n);
}